// round 16
// baseline (speedup 1.0000x reference)
#include <cuda_runtime.h>
#include <cuda_bf16.h>
#include <math.h>

// ---------------------------------------------------------------------------
// Problem constants
// ---------------------------------------------------------------------------
#define T_STEPS 512          // L*N = 64*8
#define HDIM    1024
#define GDIM    4096         // 4*H
#define VOCAB   32000
#define NCTA    128          // recurrence CTAs (<= 148 SMs -> all co-resident)

#define CANARY_U 0x7fc00001u // NaN bit pattern; h = o*tanh(c) can never be NaN

// ---------------------------------------------------------------------------
// Device scratch (static allocation allowed; cudaMalloc is not)
// ---------------------------------------------------------------------------
__device__ float g_seq[T_STEPS * HDIM];     // 2 MB  embedding sequence
__device__ float g_X  [T_STEPS * GDIM];     // 8 MB  precomputed W_ih@x + biases
__device__ float g_H0 [T_STEPS * HDIM];     // 2 MB  layer-0 hidden states
__device__ float g_H1 [T_STEPS * HDIM];     // 2 MB  layer-1 hidden states

// ---------------------------------------------------------------------------
// f32x2 packed-FMA helpers (sm_100+)
// ---------------------------------------------------------------------------
__device__ __forceinline__ unsigned long long pack2(float lo, float hi) {
    unsigned long long r;
    asm("mov.b64 %0, {%1, %2};" : "=l"(r) : "f"(lo), "f"(hi));
    return r;
}
__device__ __forceinline__ void unpack2(unsigned long long v, float& lo, float& hi) {
    asm("mov.b64 {%0, %1}, %2;" : "=f"(lo), "=f"(hi) : "l"(v));
}
__device__ __forceinline__ unsigned long long fma2(unsigned long long a,
                                                   unsigned long long b,
                                                   unsigned long long c) {
    unsigned long long d;
    asm("fma.rn.f32x2 %0, %1, %2, %3;" : "=l"(d) : "l"(a), "l"(b), "l"(c));
    return d;
}

// fast sigmoid via MUFU; tanh(x) = 2*sigmoid(2x) - 1
__device__ __forceinline__ float fsig(float x) {
    return __fdividef(1.f, 1.f + __expf(-x));
}

// ---------------------------------------------------------------------------
// Canary fill for H0/H1 (runs inside the graph; replays re-arm it)
// ---------------------------------------------------------------------------
__global__ void canary_kernel() {
    unsigned idx = blockIdx.x * blockDim.x + threadIdx.x;   // 512*256 float4s
    float c = __uint_as_float(CANARY_U);
    float4 cv = make_float4(c, c, c, c);
    ((float4*)g_H0)[idx] = cv;
    ((float4*)g_H1)[idx] = cv;
}

// ---------------------------------------------------------------------------
// Embedding gather: seq[t] = emb[x[n, l]],  t = l*8 + n
// ---------------------------------------------------------------------------
__global__ void embed_kernel(const int* __restrict__ x, const float* __restrict__ emb) {
    int t = blockIdx.x;
    int n = t & 7;
    int l = t >> 3;
    int tok = x[n * 64 + l];
    const float4* src = (const float4*)(emb + (size_t)tok * HDIM);
    ((float4*)(g_seq + (size_t)t * HDIM))[threadIdx.x] = src[threadIdx.x];
}

// ---------------------------------------------------------------------------
// NT GEMM:  C = A @ B^T + bias1 (+ bias2).  128x128x16 tiles, f32x2 FMA.
//  * A stored in SMEM as DUPLICATED pairs (a,a) -> FMA2 operand loads need
//    zero pack MOVs (dup side of the outer product comes straight from LDS)
//  * XOR-swizzled columns on both tiles -> LDS phases at the byte floor
//  * double-buffered SMEM: one __syncthreads per K-iter, LDG prefetch and
//    STS staging overlapped with compute
// ---------------------------------------------------------------------------
__global__ void __launch_bounds__(256, 2) gemm_nt_bias(
    const float* __restrict__ A, const float* __restrict__ B,
    const float* __restrict__ bias1, const float* __restrict__ bias2,
    float* __restrict__ C, int M, int N, int K)
{
    __shared__ float2 As2[2][16][128];   // dup pairs, swizzled cols: 32 KB
    __shared__ float  Bs [2][16][128];   // swizzled cols:            16 KB

    const int tid = threadIdx.x;
    const int tx = tid & 15;             // n-block
    const int ty = tid >> 4;             // m-block
    const int bm = blockIdx.y * 128;
    const int bn = blockIdx.x * 128;

    // ---- writer indices: thread covers row ar, k-cols [ac0*4, ac0*4+8) ----
    const int ar  = tid >> 1;            // 0..127
    const int ac0 = (tid & 1) * 2;       // 0 or 2  (float4 k-chunk)
    const float* ap = A + (size_t)(bm + ar) * K + ac0 * 4;
    const float* bp = B + (size_t)(bn + ar) * K + ac0 * 4;
    const int colA = ar ^ ((ar >> 3) & 14);       // swizzled m-column (float2 units)
    const int colB = ar ^ ((ar >> 4) << 2);       // swizzled n-column (float units)

    // ---- reader offsets (constant per thread; row base added per kk) ----
    int aOff[4], bOff[2];
    #pragma unroll
    for (int j = 0; j < 4; j++)
        aOff[j] = ((ty * 8 + 2 * j) ^ (ty & 14)) >> 1;          // double2 units (64/row)
    #pragma unroll
    for (int j = 0; j < 2; j++)
        bOff[j] = ((tx * 8 + 4 * j) ^ ((tx >> 1) << 2)) >> 2;   // double2 units (32/row)

    unsigned long long acc[8][4];
    #pragma unroll
    for (int i = 0; i < 8; i++)
        #pragma unroll
        for (int j = 0; j < 4; j++) acc[i][j] = 0ull;

    // prefetch tile 0
    float4 pa0 = *(const float4*)(ap);
    float4 pa1 = *(const float4*)(ap + 4);
    float4 pb0 = *(const float4*)(bp);
    float4 pb1 = *(const float4*)(bp + 4);

    // stage tile 0 into buffer 0
    {
        float2 (*Ad)[128] = As2[0];
        float  (*Bd)[128] = Bs[0];
        int r = ac0 * 4;
        Ad[r + 0][colA] = make_float2(pa0.x, pa0.x);
        Ad[r + 1][colA] = make_float2(pa0.y, pa0.y);
        Ad[r + 2][colA] = make_float2(pa0.z, pa0.z);
        Ad[r + 3][colA] = make_float2(pa0.w, pa0.w);
        Ad[r + 4][colA] = make_float2(pa1.x, pa1.x);
        Ad[r + 5][colA] = make_float2(pa1.y, pa1.y);
        Ad[r + 6][colA] = make_float2(pa1.z, pa1.z);
        Ad[r + 7][colA] = make_float2(pa1.w, pa1.w);
        Bd[r + 0][colB] = pb0.x;  Bd[r + 1][colB] = pb0.y;
        Bd[r + 2][colB] = pb0.z;  Bd[r + 3][colB] = pb0.w;
        Bd[r + 4][colB] = pb1.x;  Bd[r + 5][colB] = pb1.y;
        Bd[r + 6][colB] = pb1.z;  Bd[r + 7][colB] = pb1.w;
    }
    __syncthreads();

    const int nIter = K >> 4;
    for (int it = 0; it < nIter; it++) {
        const int buf = it & 1;

        // prefetch next tile into registers (hidden behind compute)
        if (it + 1 < nIter) {
            int k0 = (it + 1) << 4;
            pa0 = *(const float4*)(ap + k0);
            pa1 = *(const float4*)(ap + k0 + 4);
            pb0 = *(const float4*)(bp + k0);
            pb1 = *(const float4*)(bp + k0 + 4);
        }

        // compute on current buffer
        #pragma unroll
        for (int kk = 0; kk < 16; kk++) {
            const double2* Ar = (const double2*)As2[buf][kk];
            const double2* Br = (const double2*)Bs[buf][kk];
            double2 a01 = Ar[aOff[0]];
            double2 a23 = Ar[aOff[1]];
            double2 a45 = Ar[aOff[2]];
            double2 a67 = Ar[aOff[3]];
            double2 b01 = Br[bOff[0]];
            double2 b23 = Br[bOff[1]];
            unsigned long long ad[8] = {
                (unsigned long long)__double_as_longlong(a01.x),
                (unsigned long long)__double_as_longlong(a01.y),
                (unsigned long long)__double_as_longlong(a23.x),
                (unsigned long long)__double_as_longlong(a23.y),
                (unsigned long long)__double_as_longlong(a45.x),
                (unsigned long long)__double_as_longlong(a45.y),
                (unsigned long long)__double_as_longlong(a67.x),
                (unsigned long long)__double_as_longlong(a67.y)};
            unsigned long long bb[4] = {
                (unsigned long long)__double_as_longlong(b01.x),
                (unsigned long long)__double_as_longlong(b01.y),
                (unsigned long long)__double_as_longlong(b23.x),
                (unsigned long long)__double_as_longlong(b23.y)};
            #pragma unroll
            for (int i = 0; i < 8; i++)
                #pragma unroll
                for (int j = 0; j < 4; j++)
                    acc[i][j] = fma2(ad[i], bb[j], acc[i][j]);
        }

        // stage next tile into the other buffer
        if (it + 1 < nIter) {
            float2 (*Ad)[128] = As2[buf ^ 1];
            float  (*Bd)[128] = Bs[buf ^ 1];
            int r = ac0 * 4;
            Ad[r + 0][colA] = make_float2(pa0.x, pa0.x);
            Ad[r + 1][colA] = make_float2(pa0.y, pa0.y);
            Ad[r + 2][colA] = make_float2(pa0.z, pa0.z);
            Ad[r + 3][colA] = make_float2(pa0.w, pa0.w);
            Ad[r + 4][colA] = make_float2(pa1.x, pa1.x);
            Ad[r + 5][colA] = make_float2(pa1.y, pa1.y);
            Ad[r + 6][colA] = make_float2(pa1.z, pa1.z);
            Ad[r + 7][colA] = make_float2(pa1.w, pa1.w);
            Bd[r + 0][colB] = pb0.x;  Bd[r + 1][colB] = pb0.y;
            Bd[r + 2][colB] = pb0.z;  Bd[r + 3][colB] = pb0.w;
            Bd[r + 4][colB] = pb1.x;  Bd[r + 5][colB] = pb1.y;
            Bd[r + 6][colB] = pb1.z;  Bd[r + 7][colB] = pb1.w;
            __syncthreads();
        }
    }

    // epilogue
    #pragma unroll
    for (int i = 0; i < 8; i++) {
        int m = bm + ty * 8 + i;
        float* crow = C + (size_t)m * N + bn + tx * 8;
        #pragma unroll
        for (int j = 0; j < 4; j++) {
            float lo, hi;
            unpack2(acc[i][j], lo, hi);
            int n = bn + tx * 8 + 2 * j;
            lo += bias1[n];
            hi += bias1[n + 1];
            if (bias2) { lo += bias2[n]; hi += bias2[n + 1]; }
            *(float2*)(crow + 2 * j) = make_float2(lo, hi);
        }
    }
}

// ---------------------------------------------------------------------------
// LSTM recurrence (r14 PROVEN version, byte-identical): register-resident
// weights, barrier-free data-as-flag exchange (atomicExch publish /
// ld.volatile canary poll), per-warp chunk gating, parallel activations.
// ---------------------------------------------------------------------------
__global__ void __launch_bounds__(256) lstm_recur_kernel(
    const float* __restrict__ Xpre,      // [512*4096] ih part + both biases
    const float* __restrict__ Whh,       // [4096*1024]
    float* __restrict__ Hout,            // [512*1024], canary-filled
    float* __restrict__ out_h,           // [1024] or null
    float* __restrict__ out_c)           // [1024] or null
{
    __shared__ float h_s[HDIM];              // current hidden state (per-warp chunks)
    __shared__ float part_s[32 * 9];         // partials, stride 9 (conflict-free)

    const int tid  = threadIdx.x;
    const int cta  = blockIdx.x;             // 0..127
    const int hb   = cta * 8;
    const int lane = tid & 31;               // row rr
    const int wrp  = tid >> 5;               // h-chunk

    // Row rr -> global row gate*1024 + hb + k   (rr = gate*8 + k)
    const int gate = lane >> 3, k = lane & 7;
    const float* wrow = Whh + (size_t)(gate * 1024 + hb + k) * HDIM + wrp * 128;

    // Load 128 weights into registers as 64 packed f32x2
    unsigned long long w2[64];
    #pragma unroll
    for (int i = 0; i < 32; i++) {
        float4 v = ((const float4*)wrow)[i];
        w2[2 * i]     = pack2(v.x, v.y);
        w2[2 * i + 1] = pack2(v.z, v.w);
    }

    // init own chunk of h to zero (warp-local; no block sync needed)
    ((float4*)h_s)[tid] = make_float4(0.f, 0.f, 0.f, 0.f);
    __syncwarp();

    float c_reg = 0.f;
    float x_cur = 0.f;
    if (wrp == 0)                         // warp0 lane rr holds X[t, row rr]
        x_cur = Xpre[(size_t)gate * 1024 + hb + k];

    const float4* h4 = (const float4*)h_s;

    for (int t = 0; t < T_STEPS; t++) {
        // matvec over own chunk: dot(W_row[128w..], h[128w..]), 4 accumulators
        unsigned long long a0 = 0ull, a1 = 0ull, a2 = 0ull, a3 = 0ull;
        #pragma unroll
        for (int i = 0; i < 32; i += 2) {
            float4 hv0 = h4[wrp * 32 + i];
            float4 hv1 = h4[wrp * 32 + i + 1];
            a0 = fma2(w2[2 * i],     pack2(hv0.x, hv0.y), a0);
            a1 = fma2(w2[2 * i + 1], pack2(hv0.z, hv0.w), a1);
            a2 = fma2(w2[2 * i + 2], pack2(hv1.x, hv1.y), a2);
            a3 = fma2(w2[2 * i + 3], pack2(hv1.z, hv1.w), a3);
        }
        float l0, h0, l1, h1, l2, h2, l3, h3;
        unpack2(a0, l0, h0); unpack2(a1, l1, h1);
        unpack2(a2, l2, h2); unpack2(a3, l3, h3);
        part_s[lane * 9 + wrp] = ((l0 + h0) + (l1 + h1)) + ((l2 + h2) + (l3 + h3));
        __syncthreads();     // all partials visible to warp 0

        if (wrp == 0) {
            // lane rr: full gate pre-activation, parallel MUFU
            float sum = x_cur;
            #pragma unroll
            for (int w = 0; w < 8; w++) sum += part_s[lane * 9 + w];
            float sv  = (gate == 2) ? 2.f * sum : sum;
            float sg  = fsig(sv);
            float val = (gate == 2) ? (2.f * sg - 1.f) : sg;   // tanh for g-gate
            // gather i,f,g,o for h-index k to all lanes (lanes 0..7 use them)
            float i_ = __shfl_sync(0xffffffffu, val, k);
            float f_ = __shfl_sync(0xffffffffu, val, k + 8);
            float g_ = __shfl_sync(0xffffffffu, val, k + 16);
            float o_ = __shfl_sync(0xffffffffu, val, k + 24);
            if (lane < 8) {
                c_reg = f_ * c_reg + i_ * g_;
                float h_new = o_ * (2.f * fsig(2.f * c_reg) - 1.f);
                // publish: LTS-performed RMW, immediately globally visible
                atomicExch(&Hout[(size_t)t * HDIM + hb + lane], h_new);
                if (t == T_STEPS - 1) {
                    if (out_h) out_h[hb + lane] = h_new;
                    if (out_c) out_c[hb + lane] = c_reg;
                }
            }
            // prefetch next step's X (latency hidden behind poll + matvec)
            if (t + 1 < T_STEPS)
                x_cur = Xpre[(size_t)(t + 1) * GDIM + (size_t)gate * 1024 + hb + k];
        }

        // per-warp chunk poll: thread tid polls its own float4 of Hout[t]
        if (t + 1 < T_STEPS) {
            const float4* src = ((const float4*)(Hout + (size_t)t * HDIM)) + tid;
            float fx, fy, fz, fw;
            for (;;) {
                asm volatile("ld.volatile.global.v4.f32 {%0,%1,%2,%3}, [%4];"
                             : "=f"(fx), "=f"(fy), "=f"(fz), "=f"(fw)
                             : "l"(src)
                             : "memory");
                if ((__float_as_uint(fx) != CANARY_U) &
                    (__float_as_uint(fy) != CANARY_U) &
                    (__float_as_uint(fz) != CANARY_U) &
                    (__float_as_uint(fw) != CANARY_U)) break;
            }
            ((float4*)h_s)[tid] = make_float4(fx, fy, fz, fw);
            __syncwarp();    // chunk complete for this warp -> next matvec may read
        }
    }
}

// ---------------------------------------------------------------------------
// Launch
// ---------------------------------------------------------------------------
extern "C" void kernel_launch(void* const* d_in, const int* in_sizes, int n_in,
                              void* d_out, int out_size) {
    const int*   x    = (const int*)  d_in[0];
    const float* emb  = (const float*)d_in[1];
    const float* W_ih = (const float*)d_in[2];
    const float* W_hh = (const float*)d_in[3];
    const float* b_ih = (const float*)d_in[4];
    const float* b_hh = (const float*)d_in[5];
    const float* W_fc = (const float*)d_in[6];
    const float* b_fc = (const float*)d_in[7];

    float* out        = (float*)d_out;
    float* out_scores = out;
    const size_t SC   = (size_t)T_STEPS * VOCAB;
    bool  has_state   = ((size_t)out_size >= SC + 4096);
    float* out_h      = has_state ? out + SC        : nullptr;
    float* out_c      = has_state ? out + SC + 2048 : nullptr;

    void *p_seq, *p_X, *p_H0, *p_H1;
    cudaGetSymbolAddress(&p_seq, g_seq);
    cudaGetSymbolAddress(&p_X,   g_X);
    cudaGetSymbolAddress(&p_H0,  g_H0);
    cudaGetSymbolAddress(&p_H1,  g_H1);
    float* seq = (float*)p_seq;
    float* X   = (float*)p_X;
    float* H0  = (float*)p_H0;
    float* H1  = (float*)p_H1;

    const size_t WSZ = (size_t)GDIM * HDIM;

    // canary-fill H0/H1 (inside the graph; replays re-arm it)
    canary_kernel<<<512, 256>>>();

    embed_kernel<<<T_STEPS, 256>>>(x, emb);

    gemm_nt_bias<<<dim3(GDIM / 128, T_STEPS / 128), 256>>>(
        seq, W_ih, b_ih, b_hh, X, T_STEPS, GDIM, HDIM);

    lstm_recur_kernel<<<NCTA, 256>>>(X, W_hh, H0, out_h, out_c);

    gemm_nt_bias<<<dim3(GDIM / 128, T_STEPS / 128), 256>>>(
        H0, W_ih + WSZ, b_ih + GDIM, b_hh + GDIM, X, T_STEPS, GDIM, HDIM);

    lstm_recur_kernel<<<NCTA, 256>>>(X, W_hh + WSZ, H1,
                                     out_h ? out_h + HDIM : nullptr,
                                     out_c ? out_c + HDIM : nullptr);

    gemm_nt_bias<<<dim3(VOCAB / 128, T_STEPS / 128), 256>>>(
        H1, W_fc, b_fc, nullptr, out_scores, T_STEPS, VOCAB, HDIM);
}